// round 2
// baseline (speedup 1.0000x reference)
#include <cuda_runtime.h>
#include <cuda_bf16.h>
#include <cstdint>
#include <cstddef>
#include <math.h>

#define B_    128
#define T_    512
#define I_    512
#define H_    512
#define NQ_   8
#define NG    1544            // 3*512 gate cols + 8 q cols
#define NGPAD 1664            // 13 * 128

// ---------------------------------------------------------------------------
// Device scratch (static globals; no allocation)
// ---------------------------------------------------------------------------
__device__ float    g_Xpre[(size_t)T_ * B_ * NG];   // [t][b][col] x-part + bias
__device__ float    g_WxAll[(size_t)I_ * NGPAD];    // x-part weights, padded cols
__device__ float    g_WhAll[(size_t)H_ * NG];       // h-part weights
__device__ float    g_biasAll[NGPAD];
__device__ unsigned g_bar_count;
__device__ unsigned g_bar_gen;

// ---------------------------------------------------------------------------
// f32x2 helpers (FFMA2 = 2x fp32 FMA throughput, PTX-only)
// ---------------------------------------------------------------------------
__device__ __forceinline__ unsigned long long pk2(float lo, float hi) {
    unsigned long long r;
    asm("mov.b64 %0, {%1, %2};" : "=l"(r) : "f"(lo), "f"(hi));
    return r;
}
__device__ __forceinline__ void fma2(unsigned long long& d,
                                     unsigned long long a, unsigned long long b) {
    asm("fma.rn.f32x2 %0, %1, %2, %0;" : "+l"(d) : "l"(a), "l"(b));
}
__device__ __forceinline__ float2 up2(unsigned long long v) {
    float lo, hi;
    asm("mov.b64 {%0, %1}, %2;" : "=f"(lo), "=f"(hi) : "l"(v));
    return make_float2(lo, hi);
}
__device__ __forceinline__ float sigm(float x) { return 1.0f / (1.0f + expf(-x)); }

// ---------------------------------------------------------------------------
// Pack: columns [0,512)=i  [512,1024)=g  [1024,1536)=o  [1536,1544)=qf, pad=0
// ---------------------------------------------------------------------------
__global__ void pack_kernel(const float* __restrict__ Wi, const float* __restrict__ bi,
                            const float* __restrict__ Wg, const float* __restrict__ bg,
                            const float* __restrict__ Wo, const float* __restrict__ bo,
                            const float* __restrict__ Wf, const float* __restrict__ bf) {
    int idx = blockIdx.x * blockDim.x + threadIdx.x;
    if (idx >= I_ * NGPAD) return;
    int k  = idx / NGPAD;
    int jp = idx % NGPAD;
    float vx = 0.f, vh = 0.f, vb = 0.f;
    if (jp < 512) {
        vx = Wi[k * 512 + jp];   vh = Wi[(512 + k) * 512 + jp];   vb = bi[jp];
    } else if (jp < 1024) {
        int j = jp - 512;
        vx = Wg[k * 512 + j];    vh = Wg[(512 + k) * 512 + j];    vb = bg[j];
    } else if (jp < 1536) {
        int j = jp - 1024;
        vx = Wo[k * 512 + j];    vh = Wo[(512 + k) * 512 + j];    vb = bo[j];
    } else if (jp < NG) {
        int j = jp - 1536;
        vx = Wf[k * NQ_ + j];    vh = Wf[(512 + k) * NQ_ + j];    vb = bf[j];
    }
    g_WxAll[(size_t)k * NGPAD + jp] = vx;
    if (jp < NG) g_WhAll[(size_t)k * NG + jp] = vh;
    if (k == 0)  g_biasAll[jp] = vb;
}

// ---------------------------------------------------------------------------
// Precompute GEMM: g_Xpre[t][b][j] = sum_k x[b][t][k]*WxAll[k][j] + bias[j]
//   A = x [65536 x 512] (row m = b*T + t), C tiles 128x128, BK=16,
//   8x8 per thread with f32x2-paired accumulators.
// ---------------------------------------------------------------------------
__global__ void __launch_bounds__(256, 2) sgemm_kernel(const float* __restrict__ A) {
    __shared__ float As[16][128];
    __shared__ float Bs[16][128];

    const int bn  = blockIdx.x;    // 0..12
    const int bm  = blockIdx.y;    // 0..511
    const int tid = threadIdx.x;

    const int arow = tid >> 2, ac4 = tid & 3;
    const int brow = tid >> 5, bc4 = tid & 31;
    const int tr   = tid >> 4, tc  = tid & 15;

    unsigned long long acc2[8][4] = {};

    const float* Ab = A + (size_t)(bm * 128) * 512;
    const float* Bb = g_WxAll + bn * 128;

    for (int k0 = 0; k0 < 512; k0 += 16) {
#pragma unroll
        for (int p = 0; p < 2; ++p) {
            int r = arow + p * 64;
            float4 v = *(const float4*)(Ab + (size_t)r * 512 + k0 + ac4 * 4);
            As[ac4 * 4 + 0][r] = v.x;
            As[ac4 * 4 + 1][r] = v.y;
            As[ac4 * 4 + 2][r] = v.z;
            As[ac4 * 4 + 3][r] = v.w;
        }
#pragma unroll
        for (int p = 0; p < 2; ++p) {
            int r = brow + p * 8;
            float4 v = *(const float4*)(Bb + (size_t)(k0 + r) * NGPAD + bc4 * 4);
            *(float4*)&Bs[r][bc4 * 4] = v;
        }
        __syncthreads();
#pragma unroll
        for (int kk = 0; kk < 16; ++kk) {
            float a[8];
            *(float4*)&a[0] = *(const float4*)&As[kk][tr * 8];
            *(float4*)&a[4] = *(const float4*)&As[kk][tr * 8 + 4];
            const unsigned long long* brw =
                reinterpret_cast<const unsigned long long*>(&Bs[kk][tc * 8]);
            unsigned long long b0 = brw[0], b1 = brw[1], b2 = brw[2], b3 = brw[3];
#pragma unroll
            for (int i = 0; i < 8; ++i) {
                unsigned long long as = pk2(a[i], a[i]);
                fma2(acc2[i][0], as, b0);
                fma2(acc2[i][1], as, b1);
                fma2(acc2[i][2], as, b2);
                fma2(acc2[i][3], as, b3);
            }
        }
        __syncthreads();
    }

#pragma unroll
    for (int i = 0; i < 8; ++i) {
        int m = bm * 128 + tr * 8 + i;
        int b = m >> 9;
        int t = m & 511;
        size_t obase = ((size_t)t * B_ + b) * NG;
#pragma unroll
        for (int jp = 0; jp < 4; ++jp) {
            float2 v = up2(acc2[i][jp]);
            int col = bn * 128 + tc * 8 + jp * 2;
            if (col < NG)     g_Xpre[obase + col]     = v.x + g_biasAll[col];
            if (col + 1 < NG) g_Xpre[obase + col + 1] = v.y + g_biasAll[col + 1];
        }
    }
}

// ---------------------------------------------------------------------------
// Persistent recurrent kernel: 128 CTAs x 256 threads.
//   CTA = btile (32 batch rows) x jtile (16 hidden cols).
//   Thread: bloc = tid>>3 (batch row), jg = tid&7 (column pair; also q index).
// ---------------------------------------------------------------------------
struct RecSmem {
    unsigned long long wp[24][514];   // gate col-pair weights: row = gate*8 + jg
    unsigned long long wfp2[8][8];    // Wfp column pairs
    float hsm[32][516];               // h_{t-1} tile
    float wfT[8][516];                // Wf h-part, transposed (q dot)
    float bfp[16];
    float qq[32][8];
    float qp[8];
    float qa[3];
    float qb[3];
};

__device__ __forceinline__ void gridbar() {
    __threadfence();
    __syncthreads();
    if (threadIdx.x == 0) {
        unsigned gen = atomicAdd(&g_bar_gen, 0u);
        if (atomicAdd(&g_bar_count, 1u) == gridDim.x - 1) {
            atomicExch(&g_bar_count, 0u);
            __threadfence();
            atomicAdd(&g_bar_gen, 1u);
        } else {
            while (atomicAdd(&g_bar_gen, 0u) == gen) { __nanosleep(32); }
        }
        __threadfence();
    }
    __syncthreads();
}

__global__ void __launch_bounds__(256, 1)
rec_kernel(const float* __restrict__ h0, const float* __restrict__ c0,
           const float* __restrict__ qnn_a, const float* __restrict__ qnn_b,
           const float* __restrict__ qparams, const float* __restrict__ Wfp,
           const float* __restrict__ bfp_g, float* __restrict__ out) {
    extern __shared__ char smraw[];
    RecSmem& S = *reinterpret_cast<RecSmem*>(smraw);

    const int tid   = threadIdx.x;
    const int btile = blockIdx.x >> 5;
    const int jtile = blockIdx.x & 31;
    const int b0    = btile * 32;
    const int j0    = jtile * 16;

    // one-time persistent weight loads
    for (int i = tid; i < 24 * 512; i += 256) {
        int pc = i >> 9;
        int k  = i & 511;
        int g  = pc >> 3, jgp = pc & 7;
        int col = g * 512 + j0 + jgp * 2;
        S.wp[pc][k] = pk2(g_WhAll[(size_t)k * NG + col],
                          g_WhAll[(size_t)k * NG + col + 1]);
    }
    for (int i = tid; i < 8 * 512; i += 256) {
        int r = i >> 9, k = i & 511;
        S.wfT[r][k] = g_WhAll[(size_t)k * NG + 1536 + r];
    }
    if (tid < 64) {
        int k2 = tid >> 3, jgp = tid & 7;
        S.wfp2[k2][jgp] = pk2(Wfp[k2 * 512 + j0 + jgp * 2],
                              Wfp[k2 * 512 + j0 + jgp * 2 + 1]);
    }
    if (tid < 16) S.bfp[tid] = bfp_g[j0 + tid];
    if (tid < 8)  S.qp[tid]  = qparams[tid];
    if (tid < 3)  { S.qa[tid] = qnn_a[tid]; S.qb[tid] = qnn_b[tid]; }

    const int bloc = tid >> 3;
    const int jg   = tid & 7;
    const int jcol = j0 + jg * 2;

    float cr0 = c0[(size_t)(b0 + bloc) * 512 + jcol];
    float cr1 = c0[(size_t)(b0 + bloc) * 512 + jcol + 1];

    __syncthreads();

    for (int t = 0; t < T_; ++t) {
        if (t) gridbar();

        const size_t xrow = ((size_t)t * B_ + (b0 + bloc)) * NG;
        const float2 preI = *(const float2*)&g_Xpre[xrow + 0 * 512 + jcol];
        const float2 preG = *(const float2*)&g_Xpre[xrow + 1 * 512 + jcol];
        const float2 preO = *(const float2*)&g_Xpre[xrow + 2 * 512 + jcol];
        const float  qx   = g_Xpre[xrow + 1536 + jg];

        // load h_{t-1} tile [32 x 512]
        const float* hbase;
        size_t hstride;
        if (t == 0) { hbase = h0 + (size_t)b0 * 512;                      hstride = 512; }
        else        { hbase = out + ((size_t)b0 * 512 + (t - 1)) * 512;   hstride = (size_t)512 * 512; }
        for (int i = tid; i < 32 * 128; i += 256) {
            int row = i >> 7;
            int c4  = i & 127;
            float4 v = *(const float4*)(hbase + (size_t)row * hstride + c4 * 4);
            *(float4*)&S.hsm[row][c4 * 4] = v;
        }
        __syncthreads();

        // fused gate GEMM (i/g/o column pairs) + q-dot
        unsigned long long aci = 0ull, acg = 0ull, aco = 0ull;
        float qacc = 0.f;
        const float* hrow = S.hsm[bloc];
        const unsigned long long* wpi = S.wp[jg];
        const unsigned long long* wpg = S.wp[8 + jg];
        const unsigned long long* wpo = S.wp[16 + jg];
        const float* wfr = S.wfT[jg];
#pragma unroll 2
        for (int k = 0; k < 512; k += 4) {
            float4 hv = *(const float4*)&hrow[k];
            ulonglong2 wi0 = *(const ulonglong2*)&wpi[k];
            ulonglong2 wi1 = *(const ulonglong2*)&wpi[k + 2];
            ulonglong2 wg0 = *(const ulonglong2*)&wpg[k];
            ulonglong2 wg1 = *(const ulonglong2*)&wpg[k + 2];
            ulonglong2 wo0 = *(const ulonglong2*)&wpo[k];
            ulonglong2 wo1 = *(const ulonglong2*)&wpo[k + 2];
            float4 wf = *(const float4*)&wfr[k];
            unsigned long long h0s = pk2(hv.x, hv.x);
            unsigned long long h1s = pk2(hv.y, hv.y);
            unsigned long long h2s = pk2(hv.z, hv.z);
            unsigned long long h3s = pk2(hv.w, hv.w);
            fma2(aci, h0s, wi0.x); fma2(aci, h1s, wi0.y);
            fma2(aci, h2s, wi1.x); fma2(aci, h3s, wi1.y);
            fma2(acg, h0s, wg0.x); fma2(acg, h1s, wg0.y);
            fma2(acg, h2s, wg1.x); fma2(acg, h3s, wg1.y);
            fma2(aco, h0s, wo0.x); fma2(aco, h1s, wo0.y);
            fma2(aco, h2s, wo1.x); fma2(aco, h3s, wo1.y);
            qacc = fmaf(hv.x, wf.x, qacc);
            qacc = fmaf(hv.y, wf.y, qacc);
            qacc = fmaf(hv.z, wf.z, qacc);
            qacc = fmaf(hv.w, wf.w, qacc);
        }

        // quantum forget gate: tanh chain + qubit params
        float qv = qacc + qx;
#pragma unroll
        for (int r = 0; r < 3; ++r) qv = tanhf(qv * S.qa[r] + S.qb[r]);
        S.qq[bloc][jg] = qv + S.qp[jg];
        __syncthreads();

        // f = sigmoid(qq @ Wfp + bfp) for this thread's column pair
        unsigned long long fac = pk2(S.bfp[jg * 2], S.bfp[jg * 2 + 1]);
        const float* qrow = S.qq[bloc];
#pragma unroll
        for (int k2 = 0; k2 < 8; ++k2) {
            unsigned long long qs = pk2(qrow[k2], qrow[k2]);
            fma2(fac, qs, S.wfp2[k2][jg]);
        }
        float2 fv = up2(fac);
        float2 iv = up2(aci), gv = up2(acg), ov = up2(aco);

        float i0 = sigm(preI.x + iv.x), i1 = sigm(preI.y + iv.y);
        float g0 = tanhf(preG.x + gv.x), g1 = tanhf(preG.y + gv.y);
        float o0 = sigm(preO.x + ov.x), o1 = sigm(preO.y + ov.y);
        float f0 = sigm(fv.x),          f1 = sigm(fv.y);

        cr0 = f0 * cr0 + i0 * g0;
        cr1 = f1 * cr1 + i1 * g1;
        float h0v = o0 * tanhf(cr0);
        float h1v = o1 * tanhf(cr1);

        *(float2*)&out[((size_t)(b0 + bloc) * 512 + t) * 512 + jcol] =
            make_float2(h0v, h1v);
    }
}

// ---------------------------------------------------------------------------
extern "C" void kernel_launch(void* const* d_in, const int* in_sizes, int n_in,
                              void* d_out, int out_size) {
    const float* x       = (const float*)d_in[0];
    const float* h0      = (const float*)d_in[1];
    const float* c0      = (const float*)d_in[2];
    const float* Wi      = (const float*)d_in[3];
    const float* bi      = (const float*)d_in[4];
    const float* Wg      = (const float*)d_in[5];
    const float* bg      = (const float*)d_in[6];
    const float* Wo      = (const float*)d_in[7];
    const float* bo      = (const float*)d_in[8];
    const float* Wf      = (const float*)d_in[9];
    const float* bf      = (const float*)d_in[10];
    const float* qnn_a   = (const float*)d_in[11];
    const float* qnn_b   = (const float*)d_in[12];
    const float* qparams = (const float*)d_in[13];
    const float* Wfp     = (const float*)d_in[14];
    const float* bfp     = (const float*)d_in[15];
    float* out = (float*)d_out;

    cudaFuncSetAttribute(rec_kernel, cudaFuncAttributeMaxDynamicSharedMemorySize,
                         (int)sizeof(RecSmem));

    pack_kernel<<<(I_ * NGPAD + 255) / 256, 256>>>(Wi, bi, Wg, bg, Wo, bo, Wf, bf);
    sgemm_kernel<<<dim3(13, 512), 256>>>(x);
    rec_kernel<<<128, 256, sizeof(RecSmem)>>>(h0, c0, qnn_a, qnn_b, qparams,
                                              Wfp, bfp, out);
}